// round 1
// baseline (speedup 1.0000x reference)
#include <cuda_runtime.h>

// Shapes (fixed per reference setup_inputs)
#define L_DIM 4
#define B_DIM 8
#define C_DIM 256
#define HW 4096                 // 64*64 spatial
#define NROWS (L_DIM * B_DIM * C_DIM)   // 8192
#define N_ELEM (NROWS * HW)             // 33,554,432

// Scratch (no allocations allowed)
__device__ float g_gap[NROWS];
__device__ float g_attn[NROWS];

// ---------------------------------------------------------------------------
// Kernel 1: GAP — one block per (l,b,c) row, reduce 4096 floats -> mean
// ---------------------------------------------------------------------------
__global__ __launch_bounds__(256) void gap_kernel(const float4* __restrict__ in4) {
    const int row = blockIdx.x;                  // 0..8191
    const float4* p = in4 + (size_t)row * (HW / 4);   // 1024 float4 per row

    float s = 0.f;
    // 1024 float4 / 256 threads = 4 iterations, fully coalesced
    #pragma unroll
    for (int i = threadIdx.x; i < HW / 4; i += 256) {
        float4 v = p[i];
        s += (v.x + v.y) + (v.z + v.w);
    }

    // warp reduce
    #pragma unroll
    for (int off = 16; off > 0; off >>= 1)
        s += __shfl_xor_sync(0xffffffffu, s, off);

    __shared__ float warp_sums[8];
    if ((threadIdx.x & 31) == 0) warp_sums[threadIdx.x >> 5] = s;
    __syncthreads();

    if (threadIdx.x < 8) {
        float t = warp_sums[threadIdx.x];
        #pragma unroll
        for (int off = 4; off > 0; off >>= 1)
            t += __shfl_xor_sync(0xffu, t, off);
        if (threadIdx.x == 0)
            g_gap[row] = t * (1.0f / (float)HW);
    }
}

// ---------------------------------------------------------------------------
// Kernel 2: scores = gap @ W^T, softmax over L per (b, d) -> g_attn[l,b,d]
// grid = B (8 blocks), block = 256 threads (thread = output channel d)
// ---------------------------------------------------------------------------
__global__ __launch_bounds__(256) void attn_kernel(const float* __restrict__ Wlin) {
    const int b = blockIdx.x;
    const int d = threadIdx.x;

    __shared__ float gap_sh[L_DIM][C_DIM];
    #pragma unroll
    for (int l = 0; l < L_DIM; ++l)
        gap_sh[l][d] = g_gap[l * (B_DIM * C_DIM) + b * C_DIM + d];
    __syncthreads();

    float acc0 = 0.f, acc1 = 0.f, acc2 = 0.f, acc3 = 0.f;
    const float* wrow = Wlin + (size_t)d * C_DIM;   // W[d, :]
    #pragma unroll 8
    for (int c = 0; c < C_DIM; ++c) {
        float w = __ldg(&wrow[c]);
        acc0 = fmaf(gap_sh[0][c], w, acc0);
        acc1 = fmaf(gap_sh[1][c], w, acc1);
        acc2 = fmaf(gap_sh[2][c], w, acc2);
        acc3 = fmaf(gap_sh[3][c], w, acc3);
    }

    // softmax across the 4 levels
    float m = fmaxf(fmaxf(acc0, acc1), fmaxf(acc2, acc3));
    float e0 = __expf(acc0 - m);
    float e1 = __expf(acc1 - m);
    float e2 = __expf(acc2 - m);
    float e3 = __expf(acc3 - m);
    float inv = 1.0f / (e0 + e1 + e2 + e3);

    const int base = b * C_DIM + d;
    g_attn[0 * (B_DIM * C_DIM) + base] = e0 * inv;
    g_attn[1 * (B_DIM * C_DIM) + base] = e1 * inv;
    g_attn[2 * (B_DIM * C_DIM) + base] = e2 * inv;
    g_attn[3 * (B_DIM * C_DIM) + base] = e3 * inv;
}

// ---------------------------------------------------------------------------
// Kernel 3: out = in * attn[row], vectorized float4
// ---------------------------------------------------------------------------
__global__ __launch_bounds__(256) void scale_kernel(const float4* __restrict__ in4,
                                                    float4* __restrict__ out4) {
    const int idx4 = blockIdx.x * 256 + threadIdx.x;   // 0 .. N_ELEM/4-1
    const int row = idx4 >> 10;                        // / (HW/4)
    const float a = g_attn[row];
    float4 v = in4[idx4];
    v.x *= a; v.y *= a; v.z *= a; v.w *= a;
    out4[idx4] = v;
}

// ---------------------------------------------------------------------------
extern "C" void kernel_launch(void* const* d_in, const int* in_sizes, int n_in,
                              void* d_out, int out_size) {
    const float4* in4 = (const float4*)d_in[0];
    const float*  Wlin = (const float*)d_in[1];
    float4* out4 = (float4*)d_out;

    gap_kernel<<<NROWS, 256>>>(in4);
    attn_kernel<<<B_DIM, 256>>>(Wlin);
    scale_kernel<<<N_ELEM / 4 / 256, 256>>>(in4, out4);
}

// round 2
// speedup vs baseline: 1.0874x; 1.0874x over previous
#include <cuda_runtime.h>

// Shapes (fixed per reference setup_inputs)
#define L_DIM 4
#define B_DIM 8
#define C_DIM 256
#define HW 4096                 // 64*64 spatial
#define NROWS (L_DIM * B_DIM * C_DIM)   // 8192
#define N_ELEM (NROWS * HW)             // 33,554,432

// Scratch (no allocations allowed)
__device__ float g_gap[NROWS];
__device__ float g_attn[NROWS];

// ---------------------------------------------------------------------------
// Kernel 1: GAP — one block per (l,b,c) row, reduce 4096 floats -> mean
// 23.2us @ 5961 GB/s (74.5% spec) — at the practical read ceiling.
// ---------------------------------------------------------------------------
__global__ __launch_bounds__(256) void gap_kernel(const float4* __restrict__ in4) {
    const int row = blockIdx.x;                       // 0..8191
    const float4* p = in4 + (size_t)row * (HW / 4);   // 1024 float4 per row

    // 4 independent loads front-loaded (MLP=4)
    float4 v0 = p[threadIdx.x];
    float4 v1 = p[threadIdx.x + 256];
    float4 v2 = p[threadIdx.x + 512];
    float4 v3 = p[threadIdx.x + 768];

    float s = ((v0.x + v0.y) + (v0.z + v0.w))
            + ((v1.x + v1.y) + (v1.z + v1.w))
            + ((v2.x + v2.y) + (v2.z + v2.w))
            + ((v3.x + v3.y) + (v3.z + v3.w));

    // warp reduce
    #pragma unroll
    for (int off = 16; off > 0; off >>= 1)
        s += __shfl_xor_sync(0xffffffffu, s, off);

    __shared__ float warp_sums[8];
    if ((threadIdx.x & 31) == 0) warp_sums[threadIdx.x >> 5] = s;
    __syncthreads();

    if (threadIdx.x < 8) {
        float t = warp_sums[threadIdx.x];
        #pragma unroll
        for (int off = 4; off > 0; off >>= 1)
            t += __shfl_xor_sync(0xffu, t, off);
        if (threadIdx.x == 0)
            g_gap[row] = t * (1.0f / (float)HW);
    }
}

// ---------------------------------------------------------------------------
// Kernel 2: scores = gap @ W^T, softmax over L per (b, d) -> g_attn[l,b,d]
// ---------------------------------------------------------------------------
__global__ __launch_bounds__(256) void attn_kernel(const float* __restrict__ Wlin) {
    const int b = blockIdx.x;
    const int d = threadIdx.x;

    __shared__ float gap_sh[L_DIM][C_DIM];
    #pragma unroll
    for (int l = 0; l < L_DIM; ++l)
        gap_sh[l][d] = g_gap[l * (B_DIM * C_DIM) + b * C_DIM + d];
    __syncthreads();

    float acc0 = 0.f, acc1 = 0.f, acc2 = 0.f, acc3 = 0.f;
    const float* wrow = Wlin + (size_t)d * C_DIM;   // W[d, :]
    #pragma unroll 8
    for (int c = 0; c < C_DIM; ++c) {
        float w = __ldg(&wrow[c]);
        acc0 = fmaf(gap_sh[0][c], w, acc0);
        acc1 = fmaf(gap_sh[1][c], w, acc1);
        acc2 = fmaf(gap_sh[2][c], w, acc2);
        acc3 = fmaf(gap_sh[3][c], w, acc3);
    }

    // softmax across the 4 levels
    float m = fmaxf(fmaxf(acc0, acc1), fmaxf(acc2, acc3));
    float e0 = __expf(acc0 - m);
    float e1 = __expf(acc1 - m);
    float e2 = __expf(acc2 - m);
    float e3 = __expf(acc3 - m);
    float inv = 1.0f / (e0 + e1 + e2 + e3);

    const int base = b * C_DIM + d;
    g_attn[0 * (B_DIM * C_DIM) + base] = e0 * inv;
    g_attn[1 * (B_DIM * C_DIM) + base] = e1 * inv;
    g_attn[2 * (B_DIM * C_DIM) + base] = e2 * inv;
    g_attn[3 * (B_DIM * C_DIM) + base] = e3 * inv;
}

// ---------------------------------------------------------------------------
// Kernel 3: out = in * attn[row].
// One block per row; 4 independent streaming LDG.128 per thread front-loaded
// (MLP=4), then 4 streaming STG.128. attn is one broadcast load per block.
// ---------------------------------------------------------------------------
__global__ __launch_bounds__(256) void scale_kernel(const float4* __restrict__ in4,
                                                    float4* __restrict__ out4) {
    const int row = blockIdx.x;                       // 0..8191
    const float a = g_attn[row];
    const float4* p = in4 + (size_t)row * (HW / 4);
    float4*       q = out4 + (size_t)row * (HW / 4);
    const int t = threadIdx.x;

    // front-load 4 independent streaming loads
    float4 v0 = __ldcs(&p[t]);
    float4 v1 = __ldcs(&p[t + 256]);
    float4 v2 = __ldcs(&p[t + 512]);
    float4 v3 = __ldcs(&p[t + 768]);

    v0.x *= a; v0.y *= a; v0.z *= a; v0.w *= a;
    v1.x *= a; v1.y *= a; v1.z *= a; v1.w *= a;
    v2.x *= a; v2.y *= a; v2.z *= a; v2.w *= a;
    v3.x *= a; v3.y *= a; v3.z *= a; v3.w *= a;

    __stcs(&q[t],       v0);
    __stcs(&q[t + 256], v1);
    __stcs(&q[t + 512], v2);
    __stcs(&q[t + 768], v3);
}

// ---------------------------------------------------------------------------
extern "C" void kernel_launch(void* const* d_in, const int* in_sizes, int n_in,
                              void* d_out, int out_size) {
    const float4* in4 = (const float4*)d_in[0];
    const float*  Wlin = (const float*)d_in[1];
    float4* out4 = (float4*)d_out;

    gap_kernel<<<NROWS, 256>>>(in4);
    attn_kernel<<<B_DIM, 256>>>(Wlin);
    scale_kernel<<<NROWS, 256>>>(in4, out4);
}

// round 3
// speedup vs baseline: 1.1154x; 1.0258x over previous
#include <cuda_runtime.h>

// Shapes (fixed per reference setup_inputs)
#define L_DIM 4
#define B_DIM 8
#define C_DIM 256
#define HW 4096                 // 64*64 spatial
#define NROWS (L_DIM * B_DIM * C_DIM)   // 8192
#define N_ELEM (NROWS * HW)             // 33,554,432

// Scratch (no allocations allowed)
__device__ float g_gap[NROWS];
__device__ float g_attn[NROWS];

// ---------------------------------------------------------------------------
// Kernel 1: GAP — one block per (l,b,c) row, reduce 4096 floats -> mean
// Default cache policy: these reads populate L2 for reuse by scale_kernel.
// ---------------------------------------------------------------------------
__global__ __launch_bounds__(256) void gap_kernel(const float4* __restrict__ in4) {
    const int row = blockIdx.x;                       // 0..8191
    const float4* p = in4 + (size_t)row * (HW / 4);   // 1024 float4 per row

    // 4 independent loads front-loaded (MLP=4)
    float4 v0 = p[threadIdx.x];
    float4 v1 = p[threadIdx.x + 256];
    float4 v2 = p[threadIdx.x + 512];
    float4 v3 = p[threadIdx.x + 768];

    float s = ((v0.x + v0.y) + (v0.z + v0.w))
            + ((v1.x + v1.y) + (v1.z + v1.w))
            + ((v2.x + v2.y) + (v2.z + v2.w))
            + ((v3.x + v3.y) + (v3.z + v3.w));

    // warp reduce
    #pragma unroll
    for (int off = 16; off > 0; off >>= 1)
        s += __shfl_xor_sync(0xffffffffu, s, off);

    __shared__ float warp_sums[8];
    if ((threadIdx.x & 31) == 0) warp_sums[threadIdx.x >> 5] = s;
    __syncthreads();

    if (threadIdx.x < 8) {
        float t = warp_sums[threadIdx.x];
        #pragma unroll
        for (int off = 4; off > 0; off >>= 1)
            t += __shfl_xor_sync(0xffu, t, off);
        if (threadIdx.x == 0)
            g_gap[row] = t * (1.0f / (float)HW);
    }
}

// ---------------------------------------------------------------------------
// Kernel 2: scores = gap @ W^T, softmax over L per (b, d) -> g_attn[l,b,d]
// ---------------------------------------------------------------------------
__global__ __launch_bounds__(256) void attn_kernel(const float* __restrict__ Wlin) {
    const int b = blockIdx.x;
    const int d = threadIdx.x;

    __shared__ float gap_sh[L_DIM][C_DIM];
    #pragma unroll
    for (int l = 0; l < L_DIM; ++l)
        gap_sh[l][d] = g_gap[l * (B_DIM * C_DIM) + b * C_DIM + d];
    __syncthreads();

    float acc0 = 0.f, acc1 = 0.f, acc2 = 0.f, acc3 = 0.f;
    const float* wrow = Wlin + (size_t)d * C_DIM;   // W[d, :]
    #pragma unroll 8
    for (int c = 0; c < C_DIM; ++c) {
        float w = __ldg(&wrow[c]);
        acc0 = fmaf(gap_sh[0][c], w, acc0);
        acc1 = fmaf(gap_sh[1][c], w, acc1);
        acc2 = fmaf(gap_sh[2][c], w, acc2);
        acc3 = fmaf(gap_sh[3][c], w, acc3);
    }

    // softmax across the 4 levels
    float m = fmaxf(fmaxf(acc0, acc1), fmaxf(acc2, acc3));
    float e0 = __expf(acc0 - m);
    float e1 = __expf(acc1 - m);
    float e2 = __expf(acc2 - m);
    float e3 = __expf(acc3 - m);
    float inv = 1.0f / (e0 + e1 + e2 + e3);

    const int base = b * C_DIM + d;
    g_attn[0 * (B_DIM * C_DIM) + base] = e0 * inv;
    g_attn[1 * (B_DIM * C_DIM) + base] = e1 * inv;
    g_attn[2 * (B_DIM * C_DIM) + base] = e2 * inv;
    g_attn[3 * (B_DIM * C_DIM) + base] = e3 * inv;
}

// ---------------------------------------------------------------------------
// Kernel 3: out = in * attn[row].
// REVERSE row order: blocks launch ~ascending bid, so we touch the rows
// gap_kernel cached most recently first -> harvest L2 hits before eviction.
// Loads: default policy (L2-hittable). Stores: streaming (evict-first) so
// the output stream doesn't evict the resident input.
// ---------------------------------------------------------------------------
__global__ __launch_bounds__(256) void scale_kernel(const float4* __restrict__ in4,
                                                    float4* __restrict__ out4) {
    const int row = (NROWS - 1) - blockIdx.x;         // reverse traversal
    const float a = g_attn[row];
    const float4* p = in4 + (size_t)row * (HW / 4);
    float4*       q = out4 + (size_t)row * (HW / 4);
    const int t = threadIdx.x;

    // front-load 4 independent loads (MLP=4), L2-hittable
    float4 v0 = p[t];
    float4 v1 = p[t + 256];
    float4 v2 = p[t + 512];
    float4 v3 = p[t + 768];

    v0.x *= a; v0.y *= a; v0.z *= a; v0.w *= a;
    v1.x *= a; v1.y *= a; v1.z *= a; v1.w *= a;
    v2.x *= a; v2.y *= a; v2.z *= a; v2.w *= a;
    v3.x *= a; v3.y *= a; v3.z *= a; v3.w *= a;

    __stcs(&q[t],       v0);
    __stcs(&q[t + 256], v1);
    __stcs(&q[t + 512], v2);
    __stcs(&q[t + 768], v3);
}

// ---------------------------------------------------------------------------
extern "C" void kernel_launch(void* const* d_in, const int* in_sizes, int n_in,
                              void* d_out, int out_size) {
    const float4* in4 = (const float4*)d_in[0];
    const float*  Wlin = (const float*)d_in[1];
    float4* out4 = (float4*)d_out;

    gap_kernel<<<NROWS, 256>>>(in4);
    attn_kernel<<<B_DIM, 256>>>(Wlin);
    scale_kernel<<<NROWS, 256>>>(in4, out4);
}